// round 5
// baseline (speedup 1.0000x reference)
#include <cuda_runtime.h>
#include <cstdint>

#define NG    1024
#define DIM   128
#define HID   512
#define MAXE  500000
#define NBH   148          // hist/scatter blocks (identical edge partition)

// ---- scratch (no allocations allowed) ----
__device__ float    d_edge_mean[NG * DIM];
__device__ float    d_nodesum[NG * DIM];
__device__ int      d_node_start[NG + 1];      // graph boundaries in sorted batch
__device__ unsigned d_gcnt[NG];                // edge counts per graph
__device__ unsigned d_goff[NG];                // bucket start offsets
__device__ unsigned d_h[NBH * NG];             // per-block histograms
__device__ unsigned d_hoff[NBH * NG];          // per-block exclusive prefixes
__device__ int      d_bucket[MAXE];            // edge ids grouped by graph

// ---------------------------------------------------------------------------
__device__ __forceinline__ int load_idx(const void* p, long long i, int idx64) {
    return idx64 ? (int)((const long long*)p)[i] : ((const int*)p)[i];
}
// dtype probe on edge_index: node ids are random nonzero ints, so
// all-zero odd 32-bit words <=> int64 storage.
__device__ __forceinline__ int probe_idx64(const void* edge_index) {
    const int* w = (const int*)edge_index;
    int all_zero = 1;
    #pragma unroll
    for (int i = 1; i < 128; i += 2) all_zero &= (w[i] == 0);
    return all_zero;
}

// ---------------------------------------------------------------------------
// 1) zero node sums
__global__ void zero_kernel() {
    int i = blockIdx.x * blockDim.x + threadIdx.x;
    ((float4*)d_nodesum)[i] = make_float4(0.f, 0.f, 0.f, 0.f);   // grid covers exactly
}

// ---------------------------------------------------------------------------
// 2) graph boundaries: node_start[g] = lower_bound(batch, g)
__global__ void bounds_kernel(const void* __restrict__ batch,
                              const void* __restrict__ edge_index,
                              int n_nodes) {
    int g = blockIdx.x * blockDim.x + threadIdx.x;
    if (g > NG) return;
    int idx64 = probe_idx64(edge_index);
    int lo = 0, hi = n_nodes;
    while (lo < hi) {
        int m = (lo + hi) >> 1;
        if (load_idx(batch, m, idx64) < g) lo = m + 1; else hi = m;
    }
    d_node_start[g] = lo;
}

// ---------------------------------------------------------------------------
// 3) node sums: warp owns 16-node contiguous chunk of sorted batch,
//    run-accumulates, one red.v4 per graph-run.
#define NCHUNK 16
__global__ void __launch_bounds__(256) node_kernel(
        const float* __restrict__ x,
        const void* __restrict__ batch,
        const void* __restrict__ edge_index,
        int n_nodes) {
    __shared__ int s_idx64;
    if (threadIdx.x == 0) s_idx64 = probe_idx64(edge_index);
    __syncthreads();
    int idx64 = s_idx64;

    int lane  = threadIdx.x & 31;
    int warpg = (blockIdx.x * blockDim.x + threadIdx.x) >> 5;
    int s = warpg * NCHUNK;
    if (s >= n_nodes) return;
    int e = s + NCHUNK; if (e > n_nodes) e = n_nodes;

    const float4* xr = (const float4*)x;
    float4 acc = make_float4(0.f, 0.f, 0.f, 0.f);
    int cur_g = load_idx(batch, s, idx64);

    for (int i = s; i < e; i++) {
        int g = load_idx(batch, i, idx64);
        if (g != cur_g) {
            float* dst = d_nodesum + (size_t)cur_g * DIM + lane * 4;
            asm volatile("red.global.add.v4.f32 [%0], {%1,%2,%3,%4};"
                         :: "l"(dst), "f"(acc.x), "f"(acc.y), "f"(acc.z), "f"(acc.w)
                         : "memory");
            acc = make_float4(0.f, 0.f, 0.f, 0.f);
            cur_g = g;
        }
        float4 v = xr[(size_t)i * 32 + lane];
        acc.x += v.x; acc.y += v.y; acc.z += v.z; acc.w += v.w;
    }
    float* dst = d_nodesum + (size_t)cur_g * DIM + lane * 4;
    asm volatile("red.global.add.v4.f32 [%0], {%1,%2,%3,%4};"
                 :: "l"(dst), "f"(acc.x), "f"(acc.y), "f"(acc.z), "f"(acc.w)
                 : "memory");
}

// smem upper-bound: largest g with ns[g] <= s  (ns ascending, 1025 entries)
__device__ __forceinline__ int ub_search(const int* ns, int s) {
    int lo = 0, hi = NG - 1;
    #pragma unroll
    for (int it = 0; it < 10; it++) {
        int mid = (lo + hi + 1) >> 1;
        if (ns[mid] <= s) lo = mid; else hi = mid - 1;
    }
    return lo;
}

// ---------------------------------------------------------------------------
// 4) hist: per-block histogram of edge graph ids (smem binary search, no gather)
__global__ void __launch_bounds__(256) hist_kernel(
        const void* __restrict__ edge_index, int n_edges) {
    __shared__ int      s_ns[NG + 1];
    __shared__ unsigned s_cnt[NG];
    __shared__ int      s_idx64;
    int tid = threadIdx.x, b = blockIdx.x;

    if (tid == 0) s_idx64 = probe_idx64(edge_index);
    for (int i = tid; i < NG + 1; i += 256) s_ns[i] = d_node_start[i];
    for (int i = tid; i < NG; i += 256) s_cnt[i] = 0u;
    __syncthreads();
    int idx64 = s_idx64;

    int epb = (n_edges + NBH - 1) / NBH;
    int e0 = b * epb, e1 = e0 + epb; if (e1 > n_edges) e1 = n_edges;

    for (int e = e0 + tid; e < e1; e += 256) {
        int src = load_idx(edge_index, e, idx64);   // row 0 of edge_index
        atomicAdd(&s_cnt[ub_search(s_ns, src)], 1u);
    }
    __syncthreads();
    for (int i = tid; i < NG; i += 256) d_h[b * NG + i] = s_cnt[i];
}

// ---------------------------------------------------------------------------
// 5) scanA: per-graph column prefix over blocks (coalesced, no aliasing)
__global__ void __launch_bounds__(256) scanA_kernel() {
    int g = blockIdx.x * 256 + threadIdx.x;     // grid 4 x 256 = 1024
    unsigned running = 0;
    #pragma unroll 4
    for (int b = 0; b < NBH; b++) {
        unsigned v = d_h[b * NG + g];
        d_hoff[b * NG + g] = running;
        running += v;
    }
    d_gcnt[g] = running;
}

// ---------------------------------------------------------------------------
// 6) scanB: exclusive scan of 1024 totals -> bucket offsets
__global__ void scanB_kernel() {
    __shared__ unsigned t[NG];
    int i = threadIdx.x;
    unsigned v = d_gcnt[i];
    t[i] = v;
    __syncthreads();
    for (int off = 1; off < NG; off <<= 1) {
        unsigned add = (i >= off) ? t[i - off] : 0u;
        __syncthreads();
        t[i] += add;
        __syncthreads();
    }
    d_goff[i] = t[i] - v;
}

// ---------------------------------------------------------------------------
// 7) scatter: edge ids into buckets; per-block bases cached in smem
__global__ void __launch_bounds__(256) scatter_kernel(
        const void* __restrict__ edge_index, int n_edges) {
    __shared__ int      s_ns[NG + 1];
    __shared__ unsigned s_base[NG];
    __shared__ unsigned s_pos[NG];
    __shared__ int      s_idx64;
    int tid = threadIdx.x, b = blockIdx.x;

    if (tid == 0) s_idx64 = probe_idx64(edge_index);
    for (int i = tid; i < NG + 1; i += 256) s_ns[i] = d_node_start[i];
    for (int i = tid; i < NG; i += 256) {
        s_base[i] = d_goff[i] + d_hoff[b * NG + i];
        s_pos[i]  = 0u;
    }
    __syncthreads();
    int idx64 = s_idx64;

    int epb = (n_edges + NBH - 1) / NBH;
    int e0 = b * epb, e1 = e0 + epb; if (e1 > n_edges) e1 = n_edges;

    for (int e = e0 + tid; e < e1; e += 256) {
        int src = load_idx(edge_index, e, idx64);
        int g   = ub_search(s_ns, src);
        unsigned pos = s_base[g] + atomicAdd(&s_pos[g], 1u);
        d_bucket[pos] = e;
    }
}

// ---------------------------------------------------------------------------
// 8) esum: atomic-free edge mean, block per graph, 2 rows in flight per warp
__global__ void __launch_bounds__(256) esum_kernel(const float* __restrict__ edge_attr) {
    int g    = blockIdx.x;
    int lane = threadIdx.x & 31;
    int w    = threadIdx.x >> 5;

    int s = (int)d_goff[g];
    int n = (int)d_gcnt[g];

    const float4* ea = (const float4*)edge_attr;
    float4 a0 = make_float4(0.f, 0.f, 0.f, 0.f);
    float4 a1 = make_float4(0.f, 0.f, 0.f, 0.f);

    int j  = w * 2;
    int c0 = (j     < n) ? d_bucket[s + j]     : -1;
    int c1 = (j + 1 < n) ? d_bucket[s + j + 1] : -1;
    for (; j < n; j += 16) {
        int f0 = (j + 16 < n) ? d_bucket[s + j + 16] : -1;
        int f1 = (j + 17 < n) ? d_bucket[s + j + 17] : -1;
        if (c0 >= 0) {
            float4 v = ea[(size_t)c0 * 32 + lane];
            a0.x += v.x; a0.y += v.y; a0.z += v.z; a0.w += v.w;
        }
        if (c1 >= 0) {
            float4 v = ea[(size_t)c1 * 32 + lane];
            a1.x += v.x; a1.y += v.y; a1.z += v.z; a1.w += v.w;
        }
        c0 = f0; c1 = f1;
    }
    a0.x += a1.x; a0.y += a1.y; a0.z += a1.z; a0.w += a1.w;

    __shared__ float4 sacc[8][32];
    sacc[w][lane] = a0;
    __syncthreads();
    if (w == 0) {
        float4 t = sacc[0][lane];
        #pragma unroll
        for (int i = 1; i < 8; i++) {
            float4 q = sacc[i][lane];
            t.x += q.x; t.y += q.y; t.z += q.z; t.w += q.w;
        }
        float inv = 1.0f / (float)(n > 0 ? n : 1);
        t.x *= inv; t.y *= inv; t.z *= inv; t.w *= inv;
        ((float4*)(d_edge_mean + (size_t)g * DIM))[lane] = t;
    }
}

// ---------------------------------------------------------------------------
// 9) MLP + residual + LayerNorm
__global__ void __launch_bounds__(256) mlp_kernel(
        const float* __restrict__ u,
        const float* __restrict__ W1, const float* __restrict__ b1,
        const float* __restrict__ W2, const float* __restrict__ b2,
        const float* __restrict__ gamma, const float* __restrict__ beta,
        float* __restrict__ out) {
    __shared__ float inp[8][3 * DIM];
    __shared__ float hbuf[8][HID];
    __shared__ float ysm[8][DIM];

    int tid = threadIdx.x;
    int g0  = blockIdx.x * 8;

    for (int idx = tid; idx < 8 * DIM; idx += 256) {
        int g = idx >> 7, d = idx & (DIM - 1);
        int gg = g0 + g;
        int nc = d_node_start[gg + 1] - d_node_start[gg];
        float ninv = 1.0f / (float)(nc > 0 ? nc : 1);
        inp[g][d]           = u[(size_t)gg * DIM + d];
        inp[g][DIM + d]     = d_edge_mean[(size_t)gg * DIM + d];
        inp[g][2 * DIM + d] = d_nodesum[(size_t)gg * DIM + d] * ninv;
    }
    __syncthreads();

    // layer 1: h = relu(inp @ W1 + b1)
    {
        float acc0[8], acc1[8];
        float bb0 = b1[tid], bb1 = b1[tid + 256];
        #pragma unroll
        for (int g = 0; g < 8; g++) { acc0[g] = bb0; acc1[g] = bb1; }

        for (int k = 0; k < 3 * DIM; k += 4) {
            float4 iv[8];
            #pragma unroll
            for (int g = 0; g < 8; g++) iv[g] = *(const float4*)&inp[g][k];
            #pragma unroll
            for (int kk = 0; kk < 4; kk++) {
                float w0 = W1[(size_t)(k + kk) * HID + tid];
                float w1 = W1[(size_t)(k + kk) * HID + tid + 256];
                #pragma unroll
                for (int g = 0; g < 8; g++) {
                    float xv = (kk == 0) ? iv[g].x : (kk == 1) ? iv[g].y
                             : (kk == 2) ? iv[g].z : iv[g].w;
                    acc0[g] = fmaf(xv, w0, acc0[g]);
                    acc1[g] = fmaf(xv, w1, acc1[g]);
                }
            }
        }
        #pragma unroll
        for (int g = 0; g < 8; g++) {
            hbuf[g][tid]       = fmaxf(acc0[g], 0.f);
            hbuf[g][tid + 256] = fmaxf(acc1[g], 0.f);
        }
    }
    __syncthreads();

    // layer 2
    {
        int g  = tid >> 5;
        int d0 = (tid & 31) * 4;
        float4 acc = *(const float4*)&b2[d0];
        for (int k = 0; k < HID; k++) {
            float hv = hbuf[g][k];
            float4 w = *(const float4*)&W2[(size_t)k * DIM + d0];
            acc.x = fmaf(hv, w.x, acc.x);
            acc.y = fmaf(hv, w.y, acc.y);
            acc.z = fmaf(hv, w.z, acc.z);
            acc.w = fmaf(hv, w.w, acc.w);
        }
        *(float4*)&ysm[g][d0] = acc;
    }
    __syncthreads();

    // residual + layernorm
    {
        int w = tid >> 5, lane = tid & 31;
        int gg = g0 + w;
        float4 v  = *(const float4*)&ysm[w][lane * 4];
        float4 uu = *(const float4*)&u[(size_t)gg * DIM + lane * 4];
        v.x += uu.x; v.y += uu.y; v.z += uu.z; v.w += uu.w;

        float sm = v.x + v.y + v.z + v.w;
        #pragma unroll
        for (int off = 16; off; off >>= 1) sm += __shfl_xor_sync(0xffffffffu, sm, off);
        float mu = sm * (1.0f / DIM);

        float dx = v.x - mu, dy = v.y - mu, dz = v.z - mu, dw = v.w - mu;
        float sq = dx * dx + dy * dy + dz * dz + dw * dw;
        #pragma unroll
        for (int off = 16; off; off >>= 1) sq += __shfl_xor_sync(0xffffffffu, sq, off);
        float rs = rsqrtf(sq * (1.0f / DIM) + 1e-5f);

        float4 gm = *(const float4*)&gamma[lane * 4];
        float4 bt = *(const float4*)&beta[lane * 4];
        float4 o;
        o.x = dx * rs * gm.x + bt.x;
        o.y = dy * rs * gm.y + bt.y;
        o.z = dz * rs * gm.z + bt.z;
        o.w = dw * rs * gm.w + bt.w;
        *(float4*)&out[(size_t)gg * DIM + lane * 4] = o;
    }
}

// ---------------------------------------------------------------------------
extern "C" void kernel_launch(void* const* d_in, const int* in_sizes, int n_in,
                              void* d_out, int out_size) {
    const float* x         = (const float*)d_in[0];
    const float* edge_attr = (const float*)d_in[1];
    const float* u         = (const float*)d_in[2];
    const float* W1        = (const float*)d_in[3];
    const float* b1        = (const float*)d_in[4];
    const float* W2        = (const float*)d_in[5];
    const float* b2        = (const float*)d_in[6];
    const float* gamma     = (const float*)d_in[7];
    const float* beta      = (const float*)d_in[8];
    const void* edge_index = d_in[9];
    const void* batch      = d_in[10];

    int n_edges = in_sizes[9] / 2;
    int n_nodes = in_sizes[10];
    float* out = (float*)d_out;

    zero_kernel<<<128, 256>>>();                                           // 1
    bounds_kernel<<<5, 256>>>(batch, edge_index, n_nodes);                 // 2
    node_kernel<<<(n_nodes + NCHUNK * 8 - 1) / (NCHUNK * 8), 256>>>(       // 3
        x, batch, edge_index, n_nodes);
    hist_kernel<<<NBH, 256>>>(edge_index, n_edges);                        // 4 <- ncu slot
    scanA_kernel<<<4, 256>>>();                                            // 5
    scanB_kernel<<<1, NG>>>();                                             // 6
    scatter_kernel<<<NBH, 256>>>(edge_index, n_edges);                     // 7
    esum_kernel<<<NG, 256>>>(edge_attr);                                   // 8
    mlp_kernel<<<NG / 8, 256>>>(u, W1, b1, W2, b2, gamma, beta, out);      // 9
}